// round 5
// baseline (speedup 1.0000x reference)
#include <cuda_runtime.h>
#include <math.h>
#include <stdint.h>

// Problem constants
#define NN      1024
#define DF      6
#define TT      60
#define HH      64
#define GG      192      // 3*H
#define RR      64
#define WPAD    68
#define NEG_VAL (-10000.0f)
#define SLOPE   0.01f

// Inter-kernel scratch (allocation-free rule: __device__ globals)
__device__ float g_h1[NN * HH];
__device__ float g_sa[NN];
__device__ float g_sb[NN];
__device__ float g_dot[NN * NN];   // 4 MB
__device__ float g_sum[NN * NN];   // 4 MB

typedef unsigned long long u64;

__device__ __forceinline__ u64 ffma2(u64 a, u64 b, u64 c) {
    u64 d;
    asm("fma.rn.f32x2 %0, %1, %2, %3;" : "=l"(d) : "l"(a), "l"(b), "l"(c));
    return d;
}
__device__ __forceinline__ float hsum2(u64 v) {
    float lo, hi;
    asm("mov.b64 {%0,%1}, %2;" : "=f"(lo), "=f"(hi) : "l"(v));
    return lo + hi;
}
__device__ __forceinline__ float tanh_fast(float x) {
    float y;
    asm("tanh.approx.f32 %0, %1;" : "=f"(y) : "f"(x));
    return y;
}
__device__ __forceinline__ float sig_fast(float x) {
    return 0.5f * tanh_fast(0.5f * x) + 0.5f;
}

// ---------------------------------------------------------------------------
// Kernel 1: fused 2-layer GRU (unchanged from R3).
// ---------------------------------------------------------------------------
#define GRU_THREADS 256
#define GRU_ROWS    8

__global__ void __launch_bounds__(GRU_THREADS, 1)
gru_kernel(const float* __restrict__ x,
           const float* __restrict__ Wih0, const float* __restrict__ Whh0,
           const float* __restrict__ bih0, const float* __restrict__ bhh0,
           const float* __restrict__ Wih1, const float* __restrict__ Whh1,
           const float* __restrict__ bih1, const float* __restrict__ bhh1,
           const float* __restrict__ Wv)
{
    extern __shared__ float smem[];
    float* sWhh0 = smem;                          // 192*68
    float* sWih1 = sWhh0 + GG * WPAD;             // 192*68
    float* sWhh1 = sWih1 + GG * WPAD;             // 192*68
    float* sWih0 = sWhh1 + GG * WPAD;             // 192*8
    float* sB    = sWih0 + GG * 8;                // 4*192
    float* sX    = sB + 4 * GG;                   // 8*360
    float* sXt   = sX + GRU_ROWS * 360;           // 2*64
    float* sH0   = sXt + 2 * 64;                  // 8*64
    float* sH1   = sH0 + GRU_ROWS * HH;           // 8*64
    float* sGX0  = sH1 + GRU_ROWS * HH;           // 8*192
    float* sGX1p = sGX0 + GRU_ROWS * GG;          // 2*8*192
    float* sGHp  = sGX1p + 2 * GRU_ROWS * GG;     // 2*8*192

    const int tid = threadIdx.x;
    const int r0  = blockIdx.x * GRU_ROWS;

    for (int i = tid; i < GG * HH; i += GRU_THREADS) {
        int o = i >> 6, k = i & 63;
        sWhh0[o * WPAD + k] = Whh0[i];
        sWih1[o * WPAD + k] = Wih1[i];
        sWhh1[o * WPAD + k] = Whh1[i];
    }
    for (int i = tid; i < GG * DF; i += GRU_THREADS) {
        int o = i / DF, d = i % DF;
        sWih0[o * 8 + d] = Wih0[i];
    }
    for (int i = tid; i < GG; i += GRU_THREADS) {
        sB[i]          = bih0[i];
        sB[GG + i]     = bhh0[i];
        sB[2 * GG + i] = bih1[i];
        sB[3 * GG + i] = bhh1[i];
    }
    for (int i = tid; i < GRU_ROWS * 360; i += GRU_THREADS) {
        int r = i / 360, c = i % 360;
        sX[i] = x[(size_t)(r0 + r) * 360 + c];
    }
    for (int i = tid; i < GRU_ROWS * HH; i += GRU_THREADS) { sH0[i] = 0.f; sH1[i] = 0.f; }
    if (tid < GRU_ROWS * DF) {
        int r = tid / DF, d = tid % DF;
        sXt[r * 8 + d] = sX[r * 360 + d * TT + 0];
    }
    __syncthreads();

    const int kh    = tid >> 7;
    const int rem   = tid & 127;
    const int rg    = rem >> 6;
    const int ot    = rem & 63;
    const int o0    = ot * 3;
    const int rbase = rg * 4;
    const int k4b   = kh * 8;

    for (int t = 0; t < TT; ++t) {
        const int cur = t & 1, nxt = cur ^ 1;

        // Phase A
        {
            if (kh == 0) {
                float ax[4][3];
                #pragma unroll
                for (int i = 0; i < 4; i++)
                    #pragma unroll
                    for (int j = 0; j < 3; j++) ax[i][j] = sB[o0 + j];
                #pragma unroll
                for (int d = 0; d < DF; d++) {
                    float wv0 = sWih0[(o0 + 0) * 8 + d];
                    float wv1 = sWih0[(o0 + 1) * 8 + d];
                    float wv2 = sWih0[(o0 + 2) * 8 + d];
                    #pragma unroll
                    for (int i = 0; i < 4; i++) {
                        float xv = sXt[cur * 64 + (rbase + i) * 8 + d];
                        ax[i][0] += xv * wv0; ax[i][1] += xv * wv1; ax[i][2] += xv * wv2;
                    }
                }
                #pragma unroll
                for (int i = 0; i < 4; i++)
                    #pragma unroll
                    for (int j = 0; j < 3; j++)
                        sGX0[(rbase + i) * GG + o0 + j] = ax[i][j];
            }

            u64 acc[4][3];
            #pragma unroll
            for (int i = 0; i < 4; i++)
                #pragma unroll
                for (int j = 0; j < 3; j++) acc[i][j] = 0ull;

            #pragma unroll
            for (int q = 0; q < 8; q++) {
                int k4 = k4b + q;
                ulonglong2 w0 = *(const ulonglong2*)&sWhh0[(o0 + 0) * WPAD + k4 * 4];
                ulonglong2 w1 = *(const ulonglong2*)&sWhh0[(o0 + 1) * WPAD + k4 * 4];
                ulonglong2 w2 = *(const ulonglong2*)&sWhh0[(o0 + 2) * WPAD + k4 * 4];
                #pragma unroll
                for (int i = 0; i < 4; i++) {
                    ulonglong2 hv = *(const ulonglong2*)&sH0[(rbase + i) * HH + k4 * 4];
                    acc[i][0] = ffma2(hv.x, w0.x, acc[i][0]);
                    acc[i][1] = ffma2(hv.x, w1.x, acc[i][1]);
                    acc[i][2] = ffma2(hv.x, w2.x, acc[i][2]);
                    acc[i][0] = ffma2(hv.y, w0.y, acc[i][0]);
                    acc[i][1] = ffma2(hv.y, w1.y, acc[i][1]);
                    acc[i][2] = ffma2(hv.y, w2.y, acc[i][2]);
                }
            }
            #pragma unroll
            for (int i = 0; i < 4; i++)
                #pragma unroll
                for (int j = 0; j < 3; j++)
                    sGHp[kh * GRU_ROWS * GG + (rbase + i) * GG + o0 + j] = hsum2(acc[i][j]);
        }
        __syncthreads();

        // Phase B
        #pragma unroll
        for (int p = 0; p < 2; p++) {
            int item = tid + p * GRU_THREADS;
            int r = item >> 6, c = item & 63;
            float xr = sGX0[r * GG + c];
            float xz = sGX0[r * GG + 64 + c];
            float xn = sGX0[r * GG + 128 + c];
            float hr = sB[GG + c]       + sGHp[r * GG + c]       + sGHp[GRU_ROWS * GG + r * GG + c];
            float hz = sB[GG + 64 + c]  + sGHp[r * GG + 64 + c]  + sGHp[GRU_ROWS * GG + r * GG + 64 + c];
            float hn = sB[GG + 128 + c] + sGHp[r * GG + 128 + c] + sGHp[GRU_ROWS * GG + r * GG + 128 + c];
            float rv = sig_fast(xr + hr);
            float zv = sig_fast(xz + hz);
            float nv = tanh_fast(xn + rv * hn);
            float h  = sH0[r * HH + c];
            sH0[r * HH + c] = (1.f - zv) * nv + zv * h;
        }
        if (t + 1 < TT && tid < GRU_ROWS * DF) {
            int r = tid / DF, d = tid % DF;
            sXt[nxt * 64 + r * 8 + d] = sX[r * 360 + d * TT + (t + 1)];
        }
        __syncthreads();

        // Phase C
        {
            u64 a2[4][3], b2[4][3];
            #pragma unroll
            for (int i = 0; i < 4; i++)
                #pragma unroll
                for (int j = 0; j < 3; j++) { a2[i][j] = 0ull; b2[i][j] = 0ull; }

            #pragma unroll
            for (int q = 0; q < 8; q++) {
                int k4 = k4b + q;
                ulonglong2 u0 = *(const ulonglong2*)&sWih1[(o0 + 0) * WPAD + k4 * 4];
                ulonglong2 u1 = *(const ulonglong2*)&sWih1[(o0 + 1) * WPAD + k4 * 4];
                ulonglong2 u2 = *(const ulonglong2*)&sWih1[(o0 + 2) * WPAD + k4 * 4];
                ulonglong2 w0 = *(const ulonglong2*)&sWhh1[(o0 + 0) * WPAD + k4 * 4];
                ulonglong2 w1 = *(const ulonglong2*)&sWhh1[(o0 + 1) * WPAD + k4 * 4];
                ulonglong2 w2 = *(const ulonglong2*)&sWhh1[(o0 + 2) * WPAD + k4 * 4];
                #pragma unroll
                for (int i = 0; i < 4; i++) {
                    ulonglong2 gv = *(const ulonglong2*)&sH0[(rbase + i) * HH + k4 * 4];
                    ulonglong2 vv = *(const ulonglong2*)&sH1[(rbase + i) * HH + k4 * 4];
                    a2[i][0] = ffma2(gv.x, u0.x, a2[i][0]);
                    a2[i][1] = ffma2(gv.x, u1.x, a2[i][1]);
                    a2[i][2] = ffma2(gv.x, u2.x, a2[i][2]);
                    b2[i][0] = ffma2(vv.x, w0.x, b2[i][0]);
                    b2[i][1] = ffma2(vv.x, w1.x, b2[i][1]);
                    b2[i][2] = ffma2(vv.x, w2.x, b2[i][2]);
                    a2[i][0] = ffma2(gv.y, u0.y, a2[i][0]);
                    a2[i][1] = ffma2(gv.y, u1.y, a2[i][1]);
                    a2[i][2] = ffma2(gv.y, u2.y, a2[i][2]);
                    b2[i][0] = ffma2(vv.y, w0.y, b2[i][0]);
                    b2[i][1] = ffma2(vv.y, w1.y, b2[i][1]);
                    b2[i][2] = ffma2(vv.y, w2.y, b2[i][2]);
                }
            }
            #pragma unroll
            for (int i = 0; i < 4; i++)
                #pragma unroll
                for (int j = 0; j < 3; j++) {
                    sGX1p[kh * GRU_ROWS * GG + (rbase + i) * GG + o0 + j] = hsum2(a2[i][j]);
                    sGHp [kh * GRU_ROWS * GG + (rbase + i) * GG + o0 + j] = hsum2(b2[i][j]);
                }
        }
        __syncthreads();

        // Phase D
        #pragma unroll
        for (int p = 0; p < 2; p++) {
            int item = tid + p * GRU_THREADS;
            int r = item >> 6, c = item & 63;
            float xr = sB[2 * GG + c]       + sGX1p[r * GG + c]       + sGX1p[GRU_ROWS * GG + r * GG + c];
            float xz = sB[2 * GG + 64 + c]  + sGX1p[r * GG + 64 + c]  + sGX1p[GRU_ROWS * GG + r * GG + 64 + c];
            float xn = sB[2 * GG + 128 + c] + sGX1p[r * GG + 128 + c] + sGX1p[GRU_ROWS * GG + r * GG + 128 + c];
            float hr = sB[3 * GG + c]       + sGHp[r * GG + c]        + sGHp[GRU_ROWS * GG + r * GG + c];
            float hz = sB[3 * GG + 64 + c]  + sGHp[r * GG + 64 + c]   + sGHp[GRU_ROWS * GG + r * GG + 64 + c];
            float hn = sB[3 * GG + 128 + c] + sGHp[r * GG + 128 + c]  + sGHp[GRU_ROWS * GG + r * GG + 128 + c];
            float rv = sig_fast(xr + hr);
            float zv = sig_fast(xz + hz);
            float nv = tanh_fast(xn + rv * hn);
            float h  = sH1[r * HH + c];
            sH1[r * HH + c] = (1.f - zv) * nv + zv * h;
        }
        __syncthreads();
    }

    for (int i = tid; i < GRU_ROWS * HH; i += GRU_THREADS)
        g_h1[(size_t)r0 * HH + i] = sH1[i];
    if (tid < GRU_ROWS) {
        float a = 0.f, b2s = 0.f;
        #pragma unroll
        for (int c = 0; c < HH; c++) {
            float h = sH1[tid * HH + c];
            a   += h * Wv[c];
            b2s += h * Wv[HH + c];
        }
        g_sa[r0 + tid] = a;
        g_sb[r0 + tid] = b2s;
    }
}

// ---------------------------------------------------------------------------
// Kernel 2: streaming rel-dot (unchanged; now overlapped with GRU).
// ---------------------------------------------------------------------------
#define RD_THREADS 256
#define RD_BLOCKS  2048

__global__ void __launch_bounds__(RD_THREADS)
reldot_kernel(const float* __restrict__ rel, const float* __restrict__ W)
{
    __shared__ float sWv[RR];
    const int tid = threadIdx.x;
    if (tid < RR) sWv[tid] = W[2 * HH + tid];
    __syncthreads();

    const int lane16 = tid & 15;
    const int grp    = tid >> 4;
    const float4 wv  = *(const float4*)&sWv[lane16 * 4];
    const int stride = RD_BLOCKS * 16;

    for (int p = blockIdx.x * 16 + grp; p < NN * NN; p += stride) {
        float4 v = *(const float4*)&rel[(size_t)p * RR + lane16 * 4];
        float dot  = v.x * wv.x + v.y * wv.y + v.z * wv.z + v.w * wv.w;
        float ssum = v.x + v.y + v.z + v.w;
        #pragma unroll
        for (int off = 8; off; off >>= 1) {
            dot  += __shfl_xor_sync(0xffffffffu, dot,  off);
            ssum += __shfl_xor_sync(0xffffffffu, ssum, off);
        }
        if (lane16 == 0) {
            g_dot[p] = dot;
            g_sum[p] = ssum;
        }
    }
}

// ---------------------------------------------------------------------------
// Kernel 3: softmax + agg + FC, 8 rows per block (h1 tile reuse 8x in smem).
// 128 blocks x 512 threads.
// ---------------------------------------------------------------------------
#define A3_THREADS 512

__global__ void __launch_bounds__(A3_THREADS)
att3_kernel(const float* __restrict__ bsc,
            const float* __restrict__ fc_w,
            const float* __restrict__ fc_b,
            float* __restrict__ out)
{
    __shared__ float sP[8 * NN];        // masked-exp numerators, 32 KB
    __shared__ float sT[64 * 64];       // h1 tile, 16 KB
    __shared__ float sWmax[16];
    __shared__ float sWsum[16];
    __shared__ float sMax[8];
    __shared__ float sDen[8];
    __shared__ float sRed[16];

    const int tid  = threadIdx.x;
    const int wid  = tid >> 5;
    const int lane = tid & 31;
    const int i0   = blockIdx.x * 8;

    // ---- softmax phase: 2 warps per row, 16 j per thread ----
    const int r    = wid >> 1;                 // 0..7
    const int part = ((wid & 1) << 5) + lane;  // 0..63
    const int i    = i0 + r;
    const float sa_i = g_sa[i];
    const float bval = bsc[0];

    float tv[16];
    float mx = -INFINITY;
    #pragma unroll
    for (int q4 = 0; q4 < 4; q4++) {
        int j = part * 16 + q4 * 4;
        float4 d4 = *(const float4*)&g_dot[(size_t)i * NN + j];
        float4 s4 = *(const float4*)&g_sum[(size_t)i * NN + j];
        #pragma unroll
        for (int e = 0; e < 4; e++) {
            float dot  = (&d4.x)[e];
            float ssum = (&s4.x)[e];
            float w = sa_i + g_sb[j + e] + dot + bval;
            w = (w >= 0.f) ? w : SLOPE * w;
            float m  = (ssum != 0.f) ? 1.f : 0.f;
            float t  = m * w;
            if (t == 0.f) t = NEG_VAL;
            // encode mask in sign of a separate slot: store t now, mask via ssum later
            tv[q4 * 4 + e] = t;
            // stash mask bit in sP temporarily (m), overwritten after exp
            sP[r * NN + j + e] = m;
        }
        mx = fmaxf(fmaxf(fmaxf(mx, (&d4.x)[0] * 0.f + tv[q4 * 4]), fmaxf(tv[q4 * 4 + 1], tv[q4 * 4 + 2])), tv[q4 * 4 + 3]);
    }
    #pragma unroll
    for (int off = 16; off; off >>= 1) mx = fmaxf(mx, __shfl_xor_sync(0xffffffffu, mx, off));
    if (lane == 0) sWmax[wid] = mx;
    __syncthreads();
    mx = fmaxf(sWmax[r * 2], sWmax[r * 2 + 1]);

    float lsum = 0.f;
    #pragma unroll
    for (int q = 0; q < 16; q++) {
        int j = part * 16 + q;
        float e = __expf(tv[q] - mx);
        lsum += e;
        sP[r * NN + j] = e * sP[r * NN + j];   // e * mask
    }
    #pragma unroll
    for (int off = 16; off; off >>= 1) lsum += __shfl_xor_sync(0xffffffffu, lsum, off);
    if (lane == 0) sWsum[wid] = lsum;
    __syncthreads();
    if (tid < 8) {
        sDen[tid] = sWsum[tid * 2] + sWsum[tid * 2 + 1];
        sMax[tid] = 0.f;
    }
    __syncthreads();

    // ---- agg GEMM: out_agg[8][64] = sP[8][1024] @ h1[1024][64], 16 j-tiles ----
    const int c  = tid & 63;
    const int rr = tid >> 6;
    float acc = 0.f;
    for (int tile = 0; tile < 16; tile++) {
        #pragma unroll
        for (int k = 0; k < 8; k++) {
            int e = tid + k * A3_THREADS;          // 0..4095
            sT[e] = g_h1[(size_t)(tile * 64) * HH + e];
        }
        __syncthreads();
        const float* pr = &sP[rr * NN + tile * 64];
        #pragma unroll 16
        for (int jj = 0; jj < 64; jj++)
            acc += pr[jj] * sT[jj * 64 + c];
        __syncthreads();
    }

    const float inv = 1.0f / sDen[rr];
    float val = g_h1[(size_t)(i0 + rr) * HH + c] * fc_w[c] + acc * inv * fc_w[HH + c];
    #pragma unroll
    for (int off = 16; off; off >>= 1) val += __shfl_xor_sync(0xffffffffu, val, off);
    if (lane == 0) sRed[wid] = val;
    __syncthreads();
    if (tid < 8)
        out[i0 + tid] = sRed[tid * 2] + sRed[tid * 2 + 1] + fc_b[0];
}

// ---------------------------------------------------------------------------
// Launch: fork reldot onto a side stream so it overlaps the GRU.
// ---------------------------------------------------------------------------
extern "C" void kernel_launch(void* const* d_in, const int* in_sizes, int n_in,
                              void* d_out, int out_size)
{
    const float* x    = (const float*)d_in[0];
    const float* rel  = (const float*)d_in[1];
    const float* W    = (const float*)d_in[2];
    const float* b    = (const float*)d_in[3];
    const float* fc_w = (const float*)d_in[4];
    const float* fc_b = (const float*)d_in[5];
    const float* Wih0 = (const float*)d_in[6];
    const float* Whh0 = (const float*)d_in[7];
    const float* bih0 = (const float*)d_in[8];
    const float* bhh0 = (const float*)d_in[9];
    const float* Wih1 = (const float*)d_in[10];
    const float* Whh1 = (const float*)d_in[11];
    const float* bih1 = (const float*)d_in[12];
    const float* bhh1 = (const float*)d_in[13];
    float* out = (float*)d_out;

    const size_t gru_smem =
        (3 * GG * WPAD + GG * 8 + 4 * GG + GRU_ROWS * 360 + 2 * 64 +
         2 * GRU_ROWS * HH + GRU_ROWS * GG + 4 * GRU_ROWS * GG) * sizeof(float);
    cudaFuncSetAttribute(gru_kernel, cudaFuncAttributeMaxDynamicSharedMemorySize,
                         (int)gru_smem);

    // Fork-join: reldot on side stream, GRU on main stream, att3 joins both.
    cudaStream_t s1;
    cudaEvent_t eFork, eJoin;
    cudaStreamCreateWithFlags(&s1, cudaStreamNonBlocking);
    cudaEventCreateWithFlags(&eFork, cudaEventDisableTiming);
    cudaEventCreateWithFlags(&eJoin, cudaEventDisableTiming);

    cudaEventRecord(eFork, 0);
    cudaStreamWaitEvent(s1, eFork, 0);

    reldot_kernel<<<RD_BLOCKS, RD_THREADS, 0, s1>>>(rel, W);
    cudaEventRecord(eJoin, s1);

    gru_kernel<<<NN / GRU_ROWS, GRU_THREADS, gru_smem>>>(
        x, Wih0, Whh0, bih0, bhh0, Wih1, Whh1, bih1, bhh1, W);

    cudaStreamWaitEvent(0, eJoin, 0);

    att3_kernel<<<NN / 8, A3_THREADS>>>(b, fc_w, fc_b, out);
}

// round 6
// speedup vs baseline: 1.0302x; 1.0302x over previous
#include <cuda_runtime.h>
#include <math.h>
#include <stdint.h>

// Problem constants
#define NN      1024
#define DF      6
#define TT      60
#define HH      64
#define GG      192      // 3*H
#define RR      64
#define WPAD    68
#define NEG_VAL (-10000.0f)
#define SLOPE   0.01f

// Inter-kernel scratch (allocation-free rule: __device__ globals)
__device__ float g_h1[NN * HH];
__device__ float g_sa[NN];
__device__ float g_sb[NN];
__device__ float g_dot[NN * NN];   // 4 MB
__device__ float g_sum[NN * NN];   // 4 MB

typedef unsigned long long u64;

__device__ __forceinline__ u64 ffma2(u64 a, u64 b, u64 c) {
    u64 d;
    asm("fma.rn.f32x2 %0, %1, %2, %3;" : "=l"(d) : "l"(a), "l"(b), "l"(c));
    return d;
}
__device__ __forceinline__ float hsum2(u64 v) {
    float lo, hi;
    asm("mov.b64 {%0,%1}, %2;" : "=f"(lo), "=f"(hi) : "l"(v));
    return lo + hi;
}
__device__ __forceinline__ float tanh_fast(float x) {
    float y;
    asm("tanh.approx.f32 %0, %1;" : "=f"(y) : "f"(x));
    return y;
}
__device__ __forceinline__ float sig_fast(float x) {
    return 0.5f * tanh_fast(0.5f * x) + 0.5f;
}

// ---------------------------------------------------------------------------
// Kernel 1: fused 2-layer GRU v2.
// 128 blocks x 8 rows, 256 threads.
// Thread owns gate rows (c, 64+c, 128+c) of column c, 4 batch rows, half-K.
// Split-K partner = lane^16  ->  shfl reduction, gates fused, no partial smem.
// h0/h1 double-buffered  ->  2 barriers per step.
// ---------------------------------------------------------------------------
#define GRU_THREADS 256
#define GRU_ROWS    8

__global__ void __launch_bounds__(GRU_THREADS, 1)
gru_kernel(const float* __restrict__ x,
           const float* __restrict__ Wih0, const float* __restrict__ Whh0,
           const float* __restrict__ bih0, const float* __restrict__ bhh0,
           const float* __restrict__ Wih1, const float* __restrict__ Whh1,
           const float* __restrict__ bih1, const float* __restrict__ bhh1,
           const float* __restrict__ Wv)
{
    extern __shared__ float smem[];
    float* sWhh0 = smem;                          // 192*68
    float* sWih1 = sWhh0 + GG * WPAD;             // 192*68
    float* sWhh1 = sWih1 + GG * WPAD;             // 192*68
    float* sWih0 = sWhh1 + GG * WPAD;             // 192*8
    float* sX    = sWih0 + GG * 8;                // 8*360
    float* sXt   = sX + GRU_ROWS * 360;           // 2*64
    float* sH0   = sXt + 2 * 64;                  // 2*8*64 (double buffer)
    float* sH1   = sH0 + 2 * GRU_ROWS * HH;       // 2*8*64

    const int tid = threadIdx.x;
    const int r0  = blockIdx.x * GRU_ROWS;

    for (int i = tid; i < GG * HH; i += GRU_THREADS) {
        int o = i >> 6, k = i & 63;
        sWhh0[o * WPAD + k] = Whh0[i];
        sWih1[o * WPAD + k] = Wih1[i];
        sWhh1[o * WPAD + k] = Whh1[i];
    }
    for (int i = tid; i < GG * DF; i += GRU_THREADS) {
        int o = i / DF, d = i % DF;
        sWih0[o * 8 + d] = Wih0[i];
    }
    for (int i = tid; i < GRU_ROWS * 360; i += GRU_THREADS) {
        int r = i / 360, cc = i % 360;
        sX[i] = x[(size_t)(r0 + r) * 360 + cc];
    }
    for (int i = tid; i < 2 * GRU_ROWS * HH; i += GRU_THREADS) { sH0[i] = 0.f; sH1[i] = 0.f; }
    if (tid < GRU_ROWS * DF) {
        int r = tid / DF, d = tid % DF;
        sXt[r * 8 + d] = sX[r * 360 + d * TT + 0];
    }

    const int lane  = tid & 31;
    const int warp  = tid >> 5;
    const int c     = (warp & 3) * 16 + (lane & 15);   // 0..63
    const int kh    = lane >> 4;                        // split-K half
    const int rbase = (warp >> 2) * 4;                  // 0 or 4
    const int k4b   = kh * 8;
    const int g0 = c, g1 = 64 + c, g2 = 128 + c;

    // per-thread biases (combined where possible)
    const float br0  = bih0[g0] + bhh0[g0];
    const float bz0  = bih0[g1] + bhh0[g1];
    const float bxn0 = bih0[g2];
    const float bhn0 = bhh0[g2];
    const float br1  = bih1[g0] + bhh1[g0];
    const float bz1  = bih1[g1] + bhh1[g1];
    const float bxn1 = bih1[g2];
    const float bhn1 = bhh1[g2];

    __syncthreads();

    for (int t = 0; t < TT; ++t) {
        const int cur = t & 1, nxt = cur ^ 1;
        float* sH0c = sH0 + cur * (GRU_ROWS * HH);
        float* sH0n = sH0 + nxt * (GRU_ROWS * HH);
        float* sH1c = sH1 + cur * (GRU_ROWS * HH);
        float* sH1n = sH1 + nxt * (GRU_ROWS * HH);

        // ================= layer 0 =================
        {
            // x-side: split D across kh (3 each)
            float xp0[4] = {0,0,0,0}, xp1[4] = {0,0,0,0}, xp2[4] = {0,0,0,0};
            #pragma unroll
            for (int dd = 0; dd < 3; dd++) {
                int d = kh * 3 + dd;
                float w0 = sWih0[g0 * 8 + d];
                float w1 = sWih0[g1 * 8 + d];
                float w2 = sWih0[g2 * 8 + d];
                #pragma unroll
                for (int i = 0; i < 4; i++) {
                    float xv = sXt[cur * 64 + (rbase + i) * 8 + d];
                    xp0[i] += xv * w0; xp1[i] += xv * w1; xp2[i] += xv * w2;
                }
            }
            // h-side: half-K gemm
            u64 a0[4] = {0,0,0,0}, a1[4] = {0,0,0,0}, a2[4] = {0,0,0,0};
            #pragma unroll
            for (int q = 0; q < 8; q++) {
                int k4 = k4b + q;
                ulonglong2 w0 = *(const ulonglong2*)&sWhh0[g0 * WPAD + k4 * 4];
                ulonglong2 w1 = *(const ulonglong2*)&sWhh0[g1 * WPAD + k4 * 4];
                ulonglong2 w2 = *(const ulonglong2*)&sWhh0[g2 * WPAD + k4 * 4];
                #pragma unroll
                for (int i = 0; i < 4; i++) {
                    ulonglong2 hv = *(const ulonglong2*)&sH0c[(rbase + i) * HH + k4 * 4];
                    a0[i] = ffma2(hv.x, w0.x, a0[i]);
                    a1[i] = ffma2(hv.x, w1.x, a1[i]);
                    a2[i] = ffma2(hv.x, w2.x, a2[i]);
                    a0[i] = ffma2(hv.y, w0.y, a0[i]);
                    a1[i] = ffma2(hv.y, w1.y, a1[i]);
                    a2[i] = ffma2(hv.y, w2.y, a2[i]);
                }
            }
            // reduce across kh partner + gates
            float hnew[4];
            #pragma unroll
            for (int i = 0; i < 4; i++) {
                float sr = xp0[i] + hsum2(a0[i]);
                float sz = xp1[i] + hsum2(a1[i]);
                float xn = xp2[i];
                float hn = hsum2(a2[i]);
                sr += __shfl_xor_sync(0xffffffffu, sr, 16);
                sz += __shfl_xor_sync(0xffffffffu, sz, 16);
                xn += __shfl_xor_sync(0xffffffffu, xn, 16);
                hn += __shfl_xor_sync(0xffffffffu, hn, 16);
                float rv = sig_fast(sr + br0);
                float zv = sig_fast(sz + bz0);
                float nv = tanh_fast(xn + bxn0 + rv * (hn + bhn0));
                float ho = sH0c[(rbase + i) * HH + c];
                hnew[i] = (1.f - zv) * nv + zv * ho;
            }
            if (kh == 0) {
                #pragma unroll
                for (int i = 0; i < 4; i++)
                    sH0n[(rbase + i) * HH + c] = hnew[i];
            }
        }
        if (t + 1 < TT && tid < GRU_ROWS * DF) {
            int r = tid / DF, d = tid % DF;
            sXt[nxt * 64 + r * 8 + d] = sX[r * 360 + d * TT + (t + 1)];
        }
        __syncthreads();

        // ================= layer 1 =================
        {
            u64 a0[4] = {0,0,0,0}, a1[4] = {0,0,0,0}, a2[4] = {0,0,0,0};
            u64 b0[4] = {0,0,0,0}, b1[4] = {0,0,0,0}, b2[4] = {0,0,0,0};
            #pragma unroll
            for (int q = 0; q < 8; q++) {
                int k4 = k4b + q;
                ulonglong2 u0 = *(const ulonglong2*)&sWih1[g0 * WPAD + k4 * 4];
                ulonglong2 u1 = *(const ulonglong2*)&sWih1[g1 * WPAD + k4 * 4];
                ulonglong2 u2 = *(const ulonglong2*)&sWih1[g2 * WPAD + k4 * 4];
                ulonglong2 w0 = *(const ulonglong2*)&sWhh1[g0 * WPAD + k4 * 4];
                ulonglong2 w1 = *(const ulonglong2*)&sWhh1[g1 * WPAD + k4 * 4];
                ulonglong2 w2 = *(const ulonglong2*)&sWhh1[g2 * WPAD + k4 * 4];
                #pragma unroll
                for (int i = 0; i < 4; i++) {
                    ulonglong2 gv = *(const ulonglong2*)&sH0n[(rbase + i) * HH + k4 * 4];
                    ulonglong2 vv = *(const ulonglong2*)&sH1c[(rbase + i) * HH + k4 * 4];
                    a0[i] = ffma2(gv.x, u0.x, a0[i]);
                    a1[i] = ffma2(gv.x, u1.x, a1[i]);
                    a2[i] = ffma2(gv.x, u2.x, a2[i]);
                    b0[i] = ffma2(vv.x, w0.x, b0[i]);
                    b1[i] = ffma2(vv.x, w1.x, b1[i]);
                    b2[i] = ffma2(vv.x, w2.x, b2[i]);
                    a0[i] = ffma2(gv.y, u0.y, a0[i]);
                    a1[i] = ffma2(gv.y, u1.y, a1[i]);
                    a2[i] = ffma2(gv.y, u2.y, a2[i]);
                    b0[i] = ffma2(vv.y, w0.y, b0[i]);
                    b1[i] = ffma2(vv.y, w1.y, b1[i]);
                    b2[i] = ffma2(vv.y, w2.y, b2[i]);
                }
            }
            #pragma unroll
            for (int i = 0; i < 4; i++) {
                float sr = hsum2(a0[i]) + hsum2(b0[i]);
                float sz = hsum2(a1[i]) + hsum2(b1[i]);
                float xn = hsum2(a2[i]);
                float hn = hsum2(b2[i]);
                sr += __shfl_xor_sync(0xffffffffu, sr, 16);
                sz += __shfl_xor_sync(0xffffffffu, sz, 16);
                xn += __shfl_xor_sync(0xffffffffu, xn, 16);
                hn += __shfl_xor_sync(0xffffffffu, hn, 16);
                float rv = sig_fast(sr + br1);
                float zv = sig_fast(sz + bz1);
                float nv = tanh_fast(xn + bxn1 + rv * (hn + bhn1));
                float ho = sH1c[(rbase + i) * HH + c];
                float hn1 = (1.f - zv) * nv + zv * ho;
                if (kh == 0)
                    sH1n[(rbase + i) * HH + c] = hn1;
            }
        }
        __syncthreads();
    }

    // final h1 lives in buffer (TT & 1)
    const float* hf = sH1 + (TT & 1) * (GRU_ROWS * HH);
    for (int i = tid; i < GRU_ROWS * HH; i += GRU_THREADS)
        g_h1[(size_t)r0 * HH + i] = hf[i];
    if (tid < GRU_ROWS) {
        float a = 0.f, b2s = 0.f;
        #pragma unroll
        for (int cc = 0; cc < HH; cc++) {
            float h = hf[tid * HH + cc];
            a   += h * Wv[cc];
            b2s += h * Wv[HH + cc];
        }
        g_sa[r0 + tid] = a;
        g_sb[r0 + tid] = b2s;
    }
}

// ---------------------------------------------------------------------------
// Kernel 2: streaming rel-dot (unchanged).
// ---------------------------------------------------------------------------
#define RD_THREADS 256
#define RD_BLOCKS  2048

__global__ void __launch_bounds__(RD_THREADS)
reldot_kernel(const float* __restrict__ rel, const float* __restrict__ W)
{
    __shared__ float sWv[RR];
    const int tid = threadIdx.x;
    if (tid < RR) sWv[tid] = W[2 * HH + tid];
    __syncthreads();

    const int lane16 = tid & 15;
    const int grp    = tid >> 4;
    const float4 wv  = *(const float4*)&sWv[lane16 * 4];
    const int stride = RD_BLOCKS * 16;

    for (int p = blockIdx.x * 16 + grp; p < NN * NN; p += stride) {
        float4 v = *(const float4*)&rel[(size_t)p * RR + lane16 * 4];
        float dot  = v.x * wv.x + v.y * wv.y + v.z * wv.z + v.w * wv.w;
        float ssum = v.x + v.y + v.z + v.w;
        #pragma unroll
        for (int off = 8; off; off >>= 1) {
            dot  += __shfl_xor_sync(0xffffffffu, dot,  off);
            ssum += __shfl_xor_sync(0xffffffffu, ssum, off);
        }
        if (lane16 == 0) {
            g_dot[p] = dot;
            g_sum[p] = ssum;
        }
    }
}

// ---------------------------------------------------------------------------
// Kernel 3: softmax + agg + FC, 8 rows per block (unchanged from R5).
// ---------------------------------------------------------------------------
#define A3_THREADS 512

__global__ void __launch_bounds__(A3_THREADS)
att3_kernel(const float* __restrict__ bsc,
            const float* __restrict__ fc_w,
            const float* __restrict__ fc_b,
            float* __restrict__ out)
{
    __shared__ float sP[8 * NN];
    __shared__ float sT[64 * 64];
    __shared__ float sWmax[16];
    __shared__ float sWsum[16];
    __shared__ float sDen[8];
    __shared__ float sRed[16];

    const int tid  = threadIdx.x;
    const int wid  = tid >> 5;
    const int lane = tid & 31;
    const int i0   = blockIdx.x * 8;

    const int r    = wid >> 1;
    const int part = ((wid & 1) << 5) + lane;
    const int i    = i0 + r;
    const float sa_i = g_sa[i];
    const float bval = bsc[0];

    float tv[16];
    float mx = -INFINITY;
    #pragma unroll
    for (int q4 = 0; q4 < 4; q4++) {
        int j = part * 16 + q4 * 4;
        float4 d4 = *(const float4*)&g_dot[(size_t)i * NN + j];
        float4 s4 = *(const float4*)&g_sum[(size_t)i * NN + j];
        #pragma unroll
        for (int e = 0; e < 4; e++) {
            float dot  = (&d4.x)[e];
            float ssum = (&s4.x)[e];
            float w = sa_i + g_sb[j + e] + dot + bval;
            w = (w >= 0.f) ? w : SLOPE * w;
            float m  = (ssum != 0.f) ? 1.f : 0.f;
            float t  = m * w;
            if (t == 0.f) t = NEG_VAL;
            tv[q4 * 4 + e] = t;
            sP[r * NN + j + e] = m;
            mx = fmaxf(mx, t);
        }
    }
    #pragma unroll
    for (int off = 16; off; off >>= 1) mx = fmaxf(mx, __shfl_xor_sync(0xffffffffu, mx, off));
    if (lane == 0) sWmax[wid] = mx;
    __syncthreads();
    mx = fmaxf(sWmax[r * 2], sWmax[r * 2 + 1]);

    float lsum = 0.f;
    #pragma unroll
    for (int q = 0; q < 16; q++) {
        int j = part * 16 + q;
        float e = __expf(tv[q] - mx);
        lsum += e;
        sP[r * NN + j] = e * sP[r * NN + j];
    }
    #pragma unroll
    for (int off = 16; off; off >>= 1) lsum += __shfl_xor_sync(0xffffffffu, lsum, off);
    if (lane == 0) sWsum[wid] = lsum;
    __syncthreads();
    if (tid < 8) sDen[tid] = sWsum[tid * 2] + sWsum[tid * 2 + 1];
    __syncthreads();

    const int c  = tid & 63;
    const int rr = tid >> 6;
    float acc = 0.f;
    for (int tile = 0; tile < 16; tile++) {
        #pragma unroll
        for (int k = 0; k < 8; k++) {
            int e = tid + k * A3_THREADS;
            sT[e] = g_h1[(size_t)(tile * 64) * HH + e];
        }
        __syncthreads();
        const float* pr = &sP[rr * NN + tile * 64];
        #pragma unroll 16
        for (int jj = 0; jj < 64; jj++)
            acc += pr[jj] * sT[jj * 64 + c];
        __syncthreads();
    }

    const float inv = 1.0f / sDen[rr];
    float val = g_h1[(size_t)(i0 + rr) * HH + c] * fc_w[c] + acc * inv * fc_w[HH + c];
    #pragma unroll
    for (int off = 16; off; off >>= 1) val += __shfl_xor_sync(0xffffffffu, val, off);
    if (lane == 0) sRed[wid] = val;
    __syncthreads();
    if (tid < 8)
        out[i0 + tid] = sRed[tid * 2] + sRed[tid * 2 + 1] + fc_b[0];
}

// ---------------------------------------------------------------------------
// Launch: fork reldot onto a side stream so it can overlap the GRU.
// ---------------------------------------------------------------------------
extern "C" void kernel_launch(void* const* d_in, const int* in_sizes, int n_in,
                              void* d_out, int out_size)
{
    const float* x    = (const float*)d_in[0];
    const float* rel  = (const float*)d_in[1];
    const float* W    = (const float*)d_in[2];
    const float* b    = (const float*)d_in[3];
    const float* fc_w = (const float*)d_in[4];
    const float* fc_b = (const float*)d_in[5];
    const float* Wih0 = (const float*)d_in[6];
    const float* Whh0 = (const float*)d_in[7];
    const float* bih0 = (const float*)d_in[8];
    const float* bhh0 = (const float*)d_in[9];
    const float* Wih1 = (const float*)d_in[10];
    const float* Whh1 = (const float*)d_in[11];
    const float* bih1 = (const float*)d_in[12];
    const float* bhh1 = (const float*)d_in[13];
    float* out = (float*)d_out;

    const size_t gru_smem =
        (3 * GG * WPAD + GG * 8 + GRU_ROWS * 360 + 2 * 64 +
         4 * GRU_ROWS * HH) * sizeof(float);
    cudaFuncSetAttribute(gru_kernel, cudaFuncAttributeMaxDynamicSharedMemorySize,
                         (int)gru_smem);

    cudaStream_t s1;
    cudaEvent_t eFork, eJoin;
    cudaStreamCreateWithFlags(&s1, cudaStreamNonBlocking);
    cudaEventCreateWithFlags(&eFork, cudaEventDisableTiming);
    cudaEventCreateWithFlags(&eJoin, cudaEventDisableTiming);

    cudaEventRecord(eFork, 0);
    cudaStreamWaitEvent(s1, eFork, 0);

    reldot_kernel<<<RD_BLOCKS, RD_THREADS, 0, s1>>>(rel, W);
    cudaEventRecord(eJoin, s1);

    gru_kernel<<<NN / GRU_ROWS, GRU_THREADS, gru_smem>>>(
        x, Wih0, Whh0, bih0, bhh0, Wih1, Whh1, bih1, bhh1, W);

    cudaStreamWaitEvent(0, eJoin, 0);

    att3_kernel<<<NN / 8, A3_THREADS>>>(b, fc_w, fc_b, out);
}